// round 7
// baseline (speedup 1.0000x reference)
#include <cuda_runtime.h>

#define H 128
#define B 1024
#define K 10
#define NSAMP (B + B * K)   // 11264
#define REL 1000
#define MARGIN 1.0f
#define CHUNK 32            // samples staged per CTA pass
#define SCORE_THREADS 256   // 8 warps; 4 samples per warp => up to 32/pass

// ---------------- global scratch ----------------
__device__ int          g_bin_start[REL + 1];
__device__ int          g_sorted_sid[NSAMP];
__device__ int          g_sorted_h[NSAMP];
__device__ int          g_sorted_t[NSAMP];
__device__ float        g_scores[NSAMP];
__device__ unsigned int g_done;   // zero-init; last CTA resets -> graph-replay safe

// ---------------- f32x2 helpers (sm_103a packed fp32) ----------------
__device__ __forceinline__ unsigned long long ffma2(unsigned long long a,
                                                    unsigned long long b,
                                                    unsigned long long c)
{
    unsigned long long d;
    asm("fma.rn.f32x2 %0, %1, %2, %3;" : "=l"(d) : "l"(a), "l"(b), "l"(c));
    return d;
}
__device__ __forceinline__ unsigned long long pack2(float f)
{
    unsigned int u = __float_as_uint(f);
    unsigned long long d;
    asm("mov.b64 %0, {%1, %1};" : "=l"(d) : "r"(u));
    return d;
}
__device__ __forceinline__ void unpack2(unsigned long long a, float& lo, float& hi)
{
    unsigned int ulo, uhi;
    asm("mov.b64 {%0, %1}, %2;" : "=r"(ulo), "=r"(uhi) : "l"(a));
    lo = __uint_as_float(ulo);
    hi = __uint_as_float(uhi);
}

// ---------------- kernel 1: hist + scan + scatter (one block) ----------------
__global__ void __launch_bounds__(1024) preproc_kernel(
    const int* __restrict__ pos_h, const int* __restrict__ pos_t, const int* __restrict__ pos_r,
    const int* __restrict__ neg_h, const int* __restrict__ neg_t, const int* __restrict__ neg_r)
{
    __shared__ int hist[1024];
    __shared__ int cnt_save[1024];
    __shared__ int cur[1024];
    const int t = threadIdx.x;
    hist[t] = 0;
    __syncthreads();

    for (int s = t; s < NSAMP; s += 1024) {
        int r = (s < B) ? pos_r[s] : neg_r[s - B];
        atomicAdd(&hist[r], 1);
    }
    __syncthreads();
    cnt_save[t] = hist[t];
    __syncthreads();

#pragma unroll
    for (int off = 1; off < 1024; off <<= 1) {
        int u = (t >= off) ? hist[t - off] : 0;
        __syncthreads();
        if (t >= off) hist[t] += u;
        __syncthreads();
    }

    if (t < REL) {
        int excl = hist[t] - cnt_save[t];
        g_bin_start[t] = excl;
        cur[t] = excl;
    }
    if (t == REL - 1) g_bin_start[REL] = hist[REL - 1];
    __syncthreads();

    // scatter
    for (int s = t; s < NSAMP; s += 1024) {
        int r, hi, ti;
        if (s < B) { r = pos_r[s]; hi = pos_h[s]; ti = pos_t[s]; }
        else       { int n = s - B; r = neg_r[n]; hi = neg_h[n]; ti = neg_t[n]; }
        int pos = atomicAdd(&cur[r], 1);
        g_sorted_sid[pos] = s;
        g_sorted_h[pos]   = hi;
        g_sorted_t[pos]   = ti;
    }
}

// ---------------- kernel 2: grouped scoring + fused loss ----------------
// dyn smem: R (64KB) + h (16KB) + t (16KB) = 96KB -> 2 CTAs/SM
#define SCORE_SMEM ((H * H + 2 * CHUNK * H) * (int)sizeof(float))

__global__ void __launch_bounds__(SCORE_THREADS) score_loss_kernel(
    const float* __restrict__ ent,
    const float* __restrict__ rel,
    float* __restrict__ out)
{
    extern __shared__ float sm[];
    float* Rsh = sm;                  // 16384 floats
    float* hsh = sm + H * H;          // CHUNK*H
    float* tsh = hsh + CHUNK * H;     // CHUNK*H
    __shared__ int ssid[CHUNK];
    __shared__ int shix[CHUNK];
    __shared__ int stix[CHUNK];
    __shared__ int s_last;

    const int r   = blockIdx.x;
    const int beg = g_bin_start[r];
    const int m   = g_bin_start[r + 1] - beg;

    const int tid  = threadIdx.x;
    const int lane = tid & 31;
    const int w    = tid >> 5;

    if (m > 0) {
        // load R (64 KB) into smem
        const float4* Rg = (const float4*)(rel + (size_t)r * (H * H));
        float4* R4 = (float4*)Rsh;
#pragma unroll
        for (int k = 0; k < (H * H) / 4 / SCORE_THREADS; ++k)   // 16 iters
            R4[k * SCORE_THREADS + tid] = Rg[k * SCORE_THREADS + tid];

        for (int base = 0; base < m; base += CHUNK) {
            const int mp  = min(m - base, CHUNK);
            const int pad = (mp + 3) & ~3;

            __syncthreads();   // prev pass done with staging / R load done
            if (tid < CHUNK) {
                if (tid < mp) {
                    ssid[tid] = g_sorted_sid[beg + base + tid];
                    shix[tid] = g_sorted_h[beg + base + tid];
                    stix[tid] = g_sorted_t[beg + base + tid];
                } else {
                    ssid[tid] = -1;
                }
            }
            __syncthreads();

            // stage h and t (zero-fill padded rows so all later reads are defined)
            for (int idx = tid; idx < pad * H; idx += SCORE_THREADS) {
                int s = idx >> 7, j = idx & (H - 1);
                hsh[idx] = (s < mp) ? ent[(size_t)shix[s] * H + j] : 0.0f;
            }
            for (int idx = tid; idx < pad * H; idx += SCORE_THREADS) {
                int s = idx >> 7, j = idx & (H - 1);
                tsh[idx] = (s < mp) ? ent[(size_t)stix[s] * H + j] : 0.0f;
            }
            __syncthreads();

            if (w * 4 < pad) {
                const float* hb = hsh + (w * 4) * H;
                const ulonglong2* __restrict__ Rv = (const ulonglong2*)Rsh;
                unsigned long long a00 = 0, a01 = 0, a10 = 0, a11 = 0;
                unsigned long long a20 = 0, a21 = 0, a30 = 0, a31 = 0;

#pragma unroll 8
                for (int i = 0; i < H; ++i) {
                    ulonglong2 rv = Rv[i * 32 + lane];
                    unsigned long long b0 = pack2(hb[i]);
                    unsigned long long b1 = pack2(hb[H + i]);
                    unsigned long long b2 = pack2(hb[2 * H + i]);
                    unsigned long long b3 = pack2(hb[3 * H + i]);
                    a00 = ffma2(rv.x, b0, a00);  a01 = ffma2(rv.y, b0, a01);
                    a10 = ffma2(rv.x, b1, a10);  a11 = ffma2(rv.y, b1, a11);
                    a20 = ffma2(rv.x, b2, a20);  a21 = ffma2(rv.y, b2, a21);
                    a30 = ffma2(rv.x, b3, a30);  a31 = ffma2(rv.y, b3, a31);
                }

#pragma unroll
                for (int s = 0; s < 4; ++s) {
                    int sg = w * 4 + s;
                    if (sg >= mp) break;
                    unsigned long long pA = (s == 0) ? a00 : (s == 1) ? a10 : (s == 2) ? a20 : a30;
                    unsigned long long pB = (s == 0) ? a01 : (s == 1) ? a11 : (s == 2) ? a21 : a31;
                    float x0, x1, x2, x3;
                    unpack2(pA, x0, x1);
                    unpack2(pB, x2, x3);
                    const float4 tv = ((const float4*)(tsh + sg * H))[lane];
                    float v = x0 * tv.x + x1 * tv.y + x2 * tv.z + x3 * tv.w;
#pragma unroll
                    for (int off = 16; off > 0; off >>= 1)
                        v += __shfl_down_sync(0xffffffffu, v, off);
                    if (lane == 0) g_scores[ssid[sg]] = v;
                }
            }
        }
    }

    // ---- completion counting; last CTA computes the loss ----
    __syncthreads();
    if (tid == 0) {
        __threadfence();
        unsigned int old = atomicAdd(&g_done, 1u);
        s_last = (old == (unsigned int)(gridDim.x - 1)) ? 1 : 0;
    }
    __syncthreads();

    if (s_last) {
        if (tid == 0) g_done = 0;   // reset for next graph replay

        float l = 0.0f;
#pragma unroll
        for (int q = 0; q < B / SCORE_THREADS; ++q) {
            const int b = q * SCORE_THREADS + tid;
            const float p = g_scores[b];
            float n = 0.0f;
#pragma unroll
            for (int k = 0; k < K; ++k)
                n += g_scores[B + b * K + k];
            n *= (1.0f / (float)K);
            l += fmaxf(n - p + MARGIN, 0.0f);
        }

#pragma unroll
        for (int off = 16; off > 0; off >>= 1)
            l += __shfl_down_sync(0xffffffffu, l, off);

        __shared__ float ws[SCORE_THREADS / 32];
        if (lane == 0) ws[w] = l;
        __syncthreads();
        if (tid < 32) {
            float v = (tid < SCORE_THREADS / 32) ? ws[tid] : 0.0f;
#pragma unroll
            for (int off = 4; off > 0; off >>= 1)
                v += __shfl_down_sync(0xffffffffu, v, off);
            if (tid == 0) out[0] = v;
        }
    }
}

// ---------------- launcher ----------------
extern "C" void kernel_launch(void* const* d_in, const int* in_sizes, int n_in,
                              void* d_out, int out_size)
{
    const float* ent   = (const float*)d_in[0];
    const float* rel   = (const float*)d_in[1];
    const int*   pos_h = (const int*)d_in[2];
    const int*   pos_t = (const int*)d_in[3];
    const int*   pos_r = (const int*)d_in[4];
    const int*   neg_h = (const int*)d_in[5];
    const int*   neg_t = (const int*)d_in[6];
    const int*   neg_r = (const int*)d_in[7];
    float* out = (float*)d_out;

    cudaFuncSetAttribute(score_loss_kernel,
                         cudaFuncAttributeMaxDynamicSharedMemorySize, SCORE_SMEM);

    preproc_kernel<<<1, 1024>>>(pos_h, pos_t, pos_r, neg_h, neg_t, neg_r);
    score_loss_kernel<<<REL, SCORE_THREADS, SCORE_SMEM>>>(ent, rel, out);
}

// round 8
// speedup vs baseline: 1.2589x; 1.2589x over previous
#include <cuda_runtime.h>
#include <cstdint>

#define H 128
#define B 1024
#define K 10
#define NSAMP (B + B * K)   // 11264
#define REL 1000
#define MARGIN 1.0f
#define TILES 4             // row-tiles per relation
#define TROWS (H / TILES)   // 32 rows per tile (16 KB)
#define CHUNK 16            // samples staged per CTA pass
#define STHREADS 128        // 4 warps; 4 samples per warp

// ---------------- global scratch ----------------
__device__ int          g_bin_start[REL + 1];
__device__ int          g_sorted_sid[NSAMP];
__device__ int          g_sorted_h[NSAMP];
__device__ int          g_sorted_t[NSAMP];
__device__ float        g_scores[NSAMP];     // accumulated by atomics
__device__ unsigned int g_done;              // zero-init; last CTA resets

// ---------------- f32x2 helpers ----------------
__device__ __forceinline__ unsigned long long ffma2(unsigned long long a,
                                                    unsigned long long b,
                                                    unsigned long long c)
{
    unsigned long long d;
    asm("fma.rn.f32x2 %0, %1, %2, %3;" : "=l"(d) : "l"(a), "l"(b), "l"(c));
    return d;
}
__device__ __forceinline__ unsigned long long pack2(float f)
{
    unsigned int u = __float_as_uint(f);
    unsigned long long d;
    asm("mov.b64 %0, {%1, %1};" : "=l"(d) : "r"(u));
    return d;
}
__device__ __forceinline__ void unpack2(unsigned long long a, float& lo, float& hi)
{
    unsigned int ulo, uhi;
    asm("mov.b64 {%0, %1}, %2;" : "=r"(ulo), "=r"(uhi) : "l"(a));
    lo = __uint_as_float(ulo);
    hi = __uint_as_float(uhi);
}

// ---------------- kernel 1: zero + hist + scan + scatter (one block) ----------------
__global__ void __launch_bounds__(1024) preproc_kernel(
    const int* __restrict__ pos_h, const int* __restrict__ pos_t, const int* __restrict__ pos_r,
    const int* __restrict__ neg_h, const int* __restrict__ neg_t, const int* __restrict__ neg_r)
{
    __shared__ int hist[1024];
    __shared__ int wsum[32];
    __shared__ int cur[1024];
    const int t    = threadIdx.x;
    const int lane = t & 31;
    const int wid  = t >> 5;

    hist[t] = 0;
    for (int s = t; s < NSAMP; s += 1024) g_scores[s] = 0.0f;
    __syncthreads();

    for (int s = t; s < NSAMP; s += 1024) {
        int r = (s < B) ? pos_r[s] : neg_r[s - B];
        atomicAdd(&hist[r], 1);
    }
    __syncthreads();

    const int cnt = hist[t];
    // inclusive warp scan
    int v = cnt;
#pragma unroll
    for (int off = 1; off < 32; off <<= 1) {
        int u = __shfl_up_sync(0xffffffffu, v, off);
        if (lane >= off) v += u;
    }
    if (lane == 31) wsum[wid] = v;
    __syncthreads();
    if (wid == 0) {
        int x = wsum[lane];
#pragma unroll
        for (int off = 1; off < 32; off <<= 1) {
            int u = __shfl_up_sync(0xffffffffu, x, off);
            if (lane >= off) x += u;
        }
        wsum[lane] = x;   // inclusive sums of warp totals
    }
    __syncthreads();

    const int excl = v - cnt + ((wid > 0) ? wsum[wid - 1] : 0);
    if (t < REL) { g_bin_start[t] = excl; cur[t] = excl; }
    if (t == REL - 1) g_bin_start[REL] = excl + cnt;
    __syncthreads();

    // scatter
    for (int s = t; s < NSAMP; s += 1024) {
        int r, hi, ti;
        if (s < B) { r = pos_r[s]; hi = pos_h[s]; ti = pos_t[s]; }
        else       { int n = s - B; r = neg_r[n]; hi = neg_h[n]; ti = neg_t[n]; }
        int pos = atomicAdd(&cur[r], 1);
        g_sorted_sid[pos] = s;
        g_sorted_h[pos]   = hi;
        g_sorted_t[pos]   = ti;
    }
}

// ---------------- kernel 2: tiled grouped scoring + fused loss ----------------
// One CTA per (relation, 32-row tile of R). static smem ~18.6KB -> 10-12 CTAs/SM.
__global__ void __launch_bounds__(STHREADS) score_loss_kernel(
    const float* __restrict__ ent,
    const float* __restrict__ rel,
    float* __restrict__ out)
{
    __shared__ float Rsh[TROWS * H];        // 16 KB
    __shared__ float hsh[CHUNK * TROWS];    // 2 KB
    __shared__ int ssid[CHUNK];
    __shared__ int shix[CHUNK];
    __shared__ int stix[CHUNK];
    __shared__ int s_last;

    const int bx  = blockIdx.x;
    const int r   = bx >> 2;          // relation
    const int c   = bx & 3;           // row-tile
    const int beg = g_bin_start[r];
    const int m   = g_bin_start[r + 1] - beg;

    const int tid  = threadIdx.x;
    const int lane = tid & 31;
    const int w    = tid >> 5;

    if (m > 0) {
        // async prefetch of the 16KB R tile (rows [c*TROWS, c*TROWS+TROWS))
        const char* Rg = (const char*)(rel + (size_t)r * (H * H) + (size_t)c * TROWS * H);
        uint32_t sR = (uint32_t)__cvta_generic_to_shared(Rsh);
#pragma unroll
        for (int k = 0; k < (TROWS * H * 4) / (16 * STHREADS); ++k) {   // 8 iters
            int off = (k * STHREADS + tid) * 16;
            asm volatile("cp.async.cg.shared.global [%0], [%1], 16;"
                         :: "r"(sR + off), "l"(Rg + off));
        }
        asm volatile("cp.async.commit_group;");

        for (int base = 0; base < m; base += CHUNK) {
            const int mp  = min(m - base, CHUNK);
            const int pad = (mp + 3) & ~3;

            __syncthreads();   // protect staging buffers from previous pass
            if (tid < CHUNK) {
                if (tid < mp) {
                    ssid[tid] = g_sorted_sid[beg + base + tid];
                    shix[tid] = g_sorted_h[beg + base + tid];
                    stix[tid] = g_sorted_t[beg + base + tid];
                } else {
                    ssid[tid] = -1; shix[tid] = 0; stix[tid] = 0;
                }
            }
            __syncthreads();

            // stage h tile-rows: hsh[s*TROWS + ii] = h_s[c*TROWS + ii]
            for (int idx = tid; idx < pad * TROWS; idx += STHREADS) {
                int s = idx >> 5, ii = idx & (TROWS - 1);
                hsh[idx] = (s < mp) ? ent[(size_t)shix[s] * H + c * TROWS + ii] : 0.0f;
            }
            if (base == 0)
                asm volatile("cp.async.wait_group 0;");
            __syncthreads();

            if (w * 4 < pad) {
                const float* hb = hsh + (w * 4) * TROWS;
                const ulonglong2* __restrict__ Rv = (const ulonglong2*)Rsh;
                unsigned long long a00 = 0, a01 = 0, a10 = 0, a11 = 0;
                unsigned long long a20 = 0, a21 = 0, a30 = 0, a31 = 0;

#pragma unroll 8
                for (int i = 0; i < TROWS; ++i) {
                    ulonglong2 rv = Rv[i * 32 + lane];
                    unsigned long long b0 = pack2(hb[i]);
                    unsigned long long b1 = pack2(hb[TROWS + i]);
                    unsigned long long b2 = pack2(hb[2 * TROWS + i]);
                    unsigned long long b3 = pack2(hb[3 * TROWS + i]);
                    a00 = ffma2(rv.x, b0, a00);  a01 = ffma2(rv.y, b0, a01);
                    a10 = ffma2(rv.x, b1, a10);  a11 = ffma2(rv.y, b1, a11);
                    a20 = ffma2(rv.x, b2, a20);  a21 = ffma2(rv.y, b2, a21);
                    a30 = ffma2(rv.x, b3, a30);  a31 = ffma2(rv.y, b3, a31);
                }

                // epilogue: dot with t read straight from gmem (coalesced 512B row)
                float4 tv0, tv1, tv2, tv3;
                int sg0 = w * 4, sg1 = sg0 + 1, sg2 = sg0 + 2, sg3 = sg0 + 3;
                tv0 = (sg0 < mp) ? ((const float4*)(ent + (size_t)stix[sg0] * H))[lane] : make_float4(0,0,0,0);
                tv1 = (sg1 < mp) ? ((const float4*)(ent + (size_t)stix[sg1] * H))[lane] : make_float4(0,0,0,0);
                tv2 = (sg2 < mp) ? ((const float4*)(ent + (size_t)stix[sg2] * H))[lane] : make_float4(0,0,0,0);
                tv3 = (sg3 < mp) ? ((const float4*)(ent + (size_t)stix[sg3] * H))[lane] : make_float4(0,0,0,0);

#pragma unroll
                for (int s = 0; s < 4; ++s) {
                    int sg = w * 4 + s;
                    if (sg >= mp) break;
                    unsigned long long pA = (s == 0) ? a00 : (s == 1) ? a10 : (s == 2) ? a20 : a30;
                    unsigned long long pB = (s == 0) ? a01 : (s == 1) ? a11 : (s == 2) ? a21 : a31;
                    float4 tv = (s == 0) ? tv0 : (s == 1) ? tv1 : (s == 2) ? tv2 : tv3;
                    float x0, x1, x2, x3;
                    unpack2(pA, x0, x1);
                    unpack2(pB, x2, x3);
                    float v = x0 * tv.x + x1 * tv.y + x2 * tv.z + x3 * tv.w;
#pragma unroll
                    for (int off = 16; off > 0; off >>= 1)
                        v += __shfl_down_sync(0xffffffffu, v, off);
                    if (lane == 0) atomicAdd(&g_scores[ssid[sg]], v);
                }
            }
        }
    }

    // ---- completion counting; last CTA computes the loss ----
    __syncthreads();
    if (tid == 0) {
        __threadfence();
        unsigned int old = atomicAdd(&g_done, 1u);
        s_last = (old == (unsigned int)(gridDim.x - 1)) ? 1 : 0;
    }
    __syncthreads();

    if (s_last) {
        if (tid == 0) { g_done = 0; __threadfence(); }

        float l = 0.0f;
#pragma unroll
        for (int q = 0; q < B / STHREADS; ++q) {
            const int b = q * STHREADS + tid;
            const float p = g_scores[b];
            float n = 0.0f;
#pragma unroll
            for (int k = 0; k < K; ++k)
                n += g_scores[B + b * K + k];
            n *= (1.0f / (float)K);
            l += fmaxf(n - p + MARGIN, 0.0f);
        }

#pragma unroll
        for (int off = 16; off > 0; off >>= 1)
            l += __shfl_down_sync(0xffffffffu, l, off);

        __shared__ float ws[STHREADS / 32];
        if (lane == 0) ws[w] = l;
        __syncthreads();
        if (tid < 32) {
            float v = (tid < STHREADS / 32) ? ws[tid] : 0.0f;
#pragma unroll
            for (int off = 2; off > 0; off >>= 1)
                v += __shfl_down_sync(0xffffffffu, v, off);
            if (tid == 0) out[0] = v;
        }
    }
}

// ---------------- launcher ----------------
extern "C" void kernel_launch(void* const* d_in, const int* in_sizes, int n_in,
                              void* d_out, int out_size)
{
    const float* ent   = (const float*)d_in[0];
    const float* rel   = (const float*)d_in[1];
    const int*   pos_h = (const int*)d_in[2];
    const int*   pos_t = (const int*)d_in[3];
    const int*   pos_r = (const int*)d_in[4];
    const int*   neg_h = (const int*)d_in[5];
    const int*   neg_t = (const int*)d_in[6];
    const int*   neg_r = (const int*)d_in[7];
    float* out = (float*)d_out;

    preproc_kernel<<<1, 1024>>>(pos_h, pos_t, pos_r, neg_h, neg_t, neg_r);
    score_loss_kernel<<<REL * TILES, STHREADS>>>(ent, rel, out);
}

// round 9
// speedup vs baseline: 1.6332x; 1.2973x over previous
#include <cuda_runtime.h>
#include <cstdint>

#define H 128
#define B 1024
#define K 10
#define NSAMP (B + B * K)   // 11264
#define REL 1000
#define MARGIN 1.0f
#define TILES 8             // row-tiles per relation
#define TROWS (H / TILES)   // 16 rows per tile (8 KB)
#define CHUNK 16            // samples staged per CTA pass
#define STHREADS 128        // 4 warps; 4 samples per warp

// ---------------- global scratch (zero-initialized at load) ----------------
__device__ int          g_hist[REL];        // zeroed by scan_kernel each run
__device__ int          g_bin_start[REL + 1];
__device__ int          g_cursor[REL];
__device__ int          g_sorted_sid[NSAMP];
__device__ int          g_sorted_h[NSAMP];
__device__ int          g_sorted_t[NSAMP];
__device__ float        g_scores[NSAMP];    // accumulated by atomics
__device__ unsigned int g_done;             // last CTA resets -> replay-safe

// ---------------- kernel 1: histogram + zero scores (44 x 256) ----------------
__global__ void __launch_bounds__(256) hist_kernel(
    const int* __restrict__ pos_r, const int* __restrict__ neg_r)
{
    const int s = blockIdx.x * 256 + threadIdx.x;   // exactly NSAMP threads
    g_scores[s] = 0.0f;
    const int r = (s < B) ? pos_r[s] : neg_r[s - B];
    atomicAdd(&g_hist[r], 1);
}

// ---------------- kernel 2: exclusive scan over 1000 bins (1 block) ----------------
__global__ void __launch_bounds__(1024) scan_kernel()
{
    __shared__ int wsum[32];
    const int t    = threadIdx.x;
    const int lane = t & 31;
    const int wid  = t >> 5;

    const int cnt = (t < REL) ? g_hist[t] : 0;
    int v = cnt;
#pragma unroll
    for (int off = 1; off < 32; off <<= 1) {
        int u = __shfl_up_sync(0xffffffffu, v, off);
        if (lane >= off) v += u;
    }
    if (lane == 31) wsum[wid] = v;
    __syncthreads();
    if (wid == 0) {
        int x = wsum[lane];
#pragma unroll
        for (int off = 1; off < 32; off <<= 1) {
            int u = __shfl_up_sync(0xffffffffu, x, off);
            if (lane >= off) x += u;
        }
        wsum[lane] = x;
    }
    __syncthreads();

    const int excl = v - cnt + ((wid > 0) ? wsum[wid - 1] : 0);
    if (t < REL) {
        g_bin_start[t] = excl;
        g_cursor[t]    = excl;
        g_hist[t]      = 0;          // ready for next graph replay
    }
    if (t == REL - 1) g_bin_start[REL] = excl + cnt;
}

// ---------------- kernel 3: scatter into bins (44 x 256) ----------------
__global__ void __launch_bounds__(256) scatter_kernel(
    const int* __restrict__ pos_h, const int* __restrict__ pos_t, const int* __restrict__ pos_r,
    const int* __restrict__ neg_h, const int* __restrict__ neg_t, const int* __restrict__ neg_r)
{
    const int s = blockIdx.x * 256 + threadIdx.x;
    int r, hi, ti;
    if (s < B) { r = pos_r[s]; hi = pos_h[s]; ti = pos_t[s]; }
    else       { int n = s - B; r = neg_r[n]; hi = neg_h[n]; ti = neg_t[n]; }
    int pos = atomicAdd(&g_cursor[r], 1);
    g_sorted_sid[pos] = s;
    g_sorted_h[pos]   = hi;
    g_sorted_t[pos]   = ti;
}

// ---------------- kernel 4: tiled grouped scoring + fused loss ----------------
// One CTA per (relation, 16-row tile of R). smem ~9.3KB; launch_bounds caps regs
// so occupancy is ~12 CTAs/SM.
__global__ void __launch_bounds__(STHREADS, 12) score_loss_kernel(
    const float* __restrict__ ent,
    const float* __restrict__ rel,
    float* __restrict__ out)
{
    __shared__ float Rsh[TROWS * H];        // 8 KB
    __shared__ float hsh[CHUNK * TROWS];    // 1 KB
    __shared__ int ssid[CHUNK];
    __shared__ int shix[CHUNK];
    __shared__ int stix[CHUNK];
    __shared__ int s_last;

    const int bx  = blockIdx.x;
    const int r   = bx >> 3;          // relation
    const int c   = bx & 7;           // row-tile
    const int beg = g_bin_start[r];
    const int m   = g_bin_start[r + 1] - beg;

    const int tid  = threadIdx.x;
    const int lane = tid & 31;
    const int w    = tid >> 5;

    if (m > 0) {
        // async prefetch of the 8KB R tile (rows [c*TROWS, c*TROWS+TROWS))
        const char* Rg = (const char*)(rel + (size_t)r * (H * H) + (size_t)c * TROWS * H);
        uint32_t sR = (uint32_t)__cvta_generic_to_shared(Rsh);
#pragma unroll
        for (int k = 0; k < (TROWS * H * 4) / (16 * STHREADS); ++k) {   // 4 iters
            int off = (k * STHREADS + tid) * 16;
            asm volatile("cp.async.cg.shared.global [%0], [%1], 16;"
                         :: "r"(sR + off), "l"(Rg + off));
        }
        asm volatile("cp.async.commit_group;");

        for (int base = 0; base < m; base += CHUNK) {
            const int mp  = min(m - base, CHUNK);
            const int pad = (mp + 3) & ~3;

            __syncthreads();   // protect staging buffers from previous pass
            if (tid < CHUNK) {
                if (tid < mp) {
                    ssid[tid] = g_sorted_sid[beg + base + tid];
                    shix[tid] = g_sorted_h[beg + base + tid];
                    stix[tid] = g_sorted_t[beg + base + tid];
                } else {
                    ssid[tid] = -1; shix[tid] = 0; stix[tid] = 0;
                }
            }
            __syncthreads();

            // stage h tile-rows: hsh[s*TROWS + ii] = h_s[c*TROWS + ii]
            for (int idx = tid; idx < pad * TROWS; idx += STHREADS) {
                int s = idx >> 4, ii = idx & (TROWS - 1);
                hsh[idx] = (s < mp) ? ent[(size_t)shix[s] * H + c * TROWS + ii] : 0.0f;
            }
            if (base == 0)
                asm volatile("cp.async.wait_group 0;");
            __syncthreads();

            if (w * 4 < pad) {
                const float* hb = hsh + (w * 4) * TROWS;
                const float4* __restrict__ R4 = (const float4*)Rsh;
                float4 a0 = make_float4(0.f, 0.f, 0.f, 0.f);
                float4 a1 = a0, a2 = a0, a3 = a0;

#pragma unroll
                for (int i = 0; i < TROWS; ++i) {
                    float4 rv = R4[i * 32 + lane];
                    float b0 = hb[i];
                    float b1 = hb[TROWS + i];
                    float b2 = hb[2 * TROWS + i];
                    float b3 = hb[3 * TROWS + i];
                    a0.x = fmaf(rv.x, b0, a0.x); a0.y = fmaf(rv.y, b0, a0.y);
                    a0.z = fmaf(rv.z, b0, a0.z); a0.w = fmaf(rv.w, b0, a0.w);
                    a1.x = fmaf(rv.x, b1, a1.x); a1.y = fmaf(rv.y, b1, a1.y);
                    a1.z = fmaf(rv.z, b1, a1.z); a1.w = fmaf(rv.w, b1, a1.w);
                    a2.x = fmaf(rv.x, b2, a2.x); a2.y = fmaf(rv.y, b2, a2.y);
                    a2.z = fmaf(rv.z, b2, a2.z); a2.w = fmaf(rv.w, b2, a2.w);
                    a3.x = fmaf(rv.x, b3, a3.x); a3.y = fmaf(rv.y, b3, a3.y);
                    a3.z = fmaf(rv.z, b3, a3.w == a3.w ? a3.z : a3.z); // keep simple
                    a3.z = fmaf(rv.z, b3, a3.z); a3.w = fmaf(rv.w, b3, a3.w);
                }

#pragma unroll
                for (int s = 0; s < 4; ++s) {
                    int sg = w * 4 + s;
                    if (sg >= mp) break;
                    float4 a = (s == 0) ? a0 : (s == 1) ? a1 : (s == 2) ? a2 : a3;
                    const float4 tv = ((const float4*)(ent + (size_t)stix[sg] * H))[lane];
                    float v = a.x * tv.x + a.y * tv.y + a.z * tv.z + a.w * tv.w;
#pragma unroll
                    for (int off = 16; off > 0; off >>= 1)
                        v += __shfl_down_sync(0xffffffffu, v, off);
                    if (lane == 0) atomicAdd(&g_scores[ssid[sg]], v);
                }
            }
        }
    }

    // ---- completion counting; last CTA computes the loss ----
    __syncthreads();
    if (tid == 0) {
        __threadfence();
        unsigned int old = atomicAdd(&g_done, 1u);
        s_last = (old == (unsigned int)(gridDim.x - 1)) ? 1 : 0;
    }
    __syncthreads();

    if (s_last) {
        if (tid == 0) { g_done = 0; __threadfence(); }

        float l = 0.0f;
#pragma unroll
        for (int q = 0; q < B / STHREADS; ++q) {
            const int b = q * STHREADS + tid;
            const float p = g_scores[b];
            float n = 0.0f;
#pragma unroll
            for (int k = 0; k < K; ++k)
                n += g_scores[B + b * K + k];
            n *= (1.0f / (float)K);
            l += fmaxf(n - p + MARGIN, 0.0f);
        }

#pragma unroll
        for (int off = 16; off > 0; off >>= 1)
            l += __shfl_down_sync(0xffffffffu, l, off);

        __shared__ float ws[STHREADS / 32];
        if (lane == 0) ws[w] = l;
        __syncthreads();
        if (tid < 32) {
            float v = (tid < STHREADS / 32) ? ws[tid] : 0.0f;
#pragma unroll
            for (int off = 2; off > 0; off >>= 1)
                v += __shfl_down_sync(0xffffffffu, v, off);
            if (tid == 0) out[0] = v;
        }
    }
}

// ---------------- launcher ----------------
extern "C" void kernel_launch(void* const* d_in, const int* in_sizes, int n_in,
                              void* d_out, int out_size)
{
    const float* ent   = (const float*)d_in[0];
    const float* rel   = (const float*)d_in[1];
    const int*   pos_h = (const int*)d_in[2];
    const int*   pos_t = (const int*)d_in[3];
    const int*   pos_r = (const int*)d_in[4];
    const int*   neg_h = (const int*)d_in[5];
    const int*   neg_t = (const int*)d_in[6];
    const int*   neg_r = (const int*)d_in[7];
    float* out = (float*)d_out;

    hist_kernel<<<NSAMP / 256, 256>>>(pos_r, neg_r);
    scan_kernel<<<1, 1024>>>();
    scatter_kernel<<<NSAMP / 256, 256>>>(pos_h, pos_t, pos_r, neg_h, neg_t, neg_r);
    score_loss_kernel<<<REL * TILES, STHREADS>>>(ent, rel, out);
}